// round 13
// baseline (speedup 1.0000x reference)
#include <cuda_runtime.h>
#include <cuda_fp16.h>
#include <cstdint>

// Problem constants
#define N_ATOMS 100000
#define N_EDGES 1000000
#define HID 64
#define OUTD 128
#define NTILES 782           // ceil(N_ATOMS / 128)
#define PROJ_GRID 148
#define PROJ_T 384

#define SCAN_T 512
#define SCAN_ITEMS (N_ATOMS + 1)
#define SCAN_NB ((SCAN_ITEMS + SCAN_T - 1) / SCAN_T)

// Scratch (device globals: allocation-free rule)
__device__ __half g_xh[N_ATOMS * HID];     // node features, fp16 (MMA A operand)
__device__ __half g_gtop[N_ATOMS * HID];   // 0.5*(x @ Wg_top + b_gate)
__device__ uint2  g_gl[N_ATOMS * 32];      // per (node,lane): {0.5*gbot half2, linh half2}
__device__ __half g_wf[3 * 64 * 192];      // fused fp16 weights per layer
__device__ float  g_pooled[HID];

// Edge CSR (built per launch by counting sort)
__device__ int g_cnt[SCAN_ITEMS];
__device__ int g_off[SCAN_ITEMS];
__device__ int g_cur[N_ATOMS];
__device__ int g_part[SCAN_NB];
__device__ int g_scol[N_EDGES];

static __device__ __forceinline__ uint32_t cvta_s(const void* p) {
    uint32_t r;
    asm("{ .reg .u64 t; cvta.to.shared.u64 t, %1; cvt.u32.u64 %0, t; }" : "=r"(r) : "l"(p));
    return r;
}

// ---------------------------------------------------------------------------
// 0. Weight preconvert + zero g_cnt/g_pooled (runs FIRST)
// ---------------------------------------------------------------------------
__global__ void __launch_bounds__(256) wconv_kernel(const float* __restrict__ Wg,
                                                    const float* __restrict__ Wl) {
    int i = blockIdx.x * 256 + threadIdx.x;
    if (i < 3 * 64 * 192) {
        int lay = i / (64 * 192);
        int rem = i - lay * (64 * 192);
        int k = rem / 192, c = rem - k * 192;
        float w;
        if (c < 64)       w = Wg[lay * 128 * 64 + k * 64 + c];
        else if (c < 128) w = Wg[lay * 128 * 64 + (64 + k) * 64 + (c - 64)];
        else              w = Wl[lay * 64 * 64 + k * 64 + (c - 128)];
        g_wf[i] = __float2half(w);
    }
    if (i < SCAN_ITEMS) g_cnt[i] = 0;
    if (i < HID) g_pooled[i] = 0.0f;
}

// ---------------------------------------------------------------------------
// 1. Embedding lookup + edge histogram
// ---------------------------------------------------------------------------
__global__ void __launch_bounds__(256) embed_kernel(const int* __restrict__ an,
                                                    const float* __restrict__ emb,
                                                    const int* __restrict__ ei) {
    int i = blockIdx.x * 256 + threadIdx.x;
    if (i < N_ATOMS * HID) {
        int v = i >> 6;
        g_xh[i] = __float2half(emb[an[v] * HID + (i & 63)]);
    }
    if (i < N_EDGES) atomicAdd(&g_cnt[ei[i]], 1);
}

// ---------------------------------------------------------------------------
// 2. Scan + scatter (counting sort by row)
// ---------------------------------------------------------------------------
__global__ void __launch_bounds__(SCAN_T) scan_a_kernel() {
    __shared__ int s[SCAN_T];
    int t = threadIdx.x;
    int i = blockIdx.x * SCAN_T + t;
    s[t] = (i < SCAN_ITEMS) ? g_cnt[i] : 0;
    __syncthreads();
    for (int d = SCAN_T / 2; d > 0; d >>= 1) {
        if (t < d) s[t] += s[t + d];
        __syncthreads();
    }
    if (t == 0) g_part[blockIdx.x] = s[0];
}

__global__ void __launch_bounds__(SCAN_T) scan_c_kernel() {
    __shared__ int s[SCAN_T];
    __shared__ int p[256];
    int t = threadIdx.x;
    int i = blockIdx.x * SCAN_T + t;

    if (t < 256) p[t] = (t < SCAN_NB) ? g_part[t] : 0;
    __syncthreads();
    for (int d = 1; d < 256; d <<= 1) {
        int a = 0;
        if (t < 256 && t >= d) a = p[t - d];
        __syncthreads();
        if (t < 256) p[t] += a;
        __syncthreads();
    }
    int prefix = (blockIdx.x == 0) ? 0 : p[blockIdx.x - 1];

    int v = (i < SCAN_ITEMS) ? g_cnt[i] : 0;
    s[t] = v;
    __syncthreads();
    for (int d = 1; d < SCAN_T; d <<= 1) {
        int a = (t >= d) ? s[t - d] : 0;
        __syncthreads();
        s[t] += a;
        __syncthreads();
    }
    int off = prefix + s[t] - v;  // exclusive
    if (i < SCAN_ITEMS) g_off[i] = off;
    if (i < N_ATOMS)    g_cur[i] = off;
}

__global__ void __launch_bounds__(256) scatter_kernel(const int* __restrict__ ei) {
    int e = blockIdx.x * 256 + threadIdx.x;
    if (e < N_EDGES) {
        int r = ei[e];
        int c = ei[N_EDGES + e];
        int p = atomicAdd(&g_cur[r], 1);
        g_scol[p] = c;
    }
}

// ---------------------------------------------------------------------------
// 3. Persistent tensor-core projection, v2.
//    384 thr, 12 warps = 4(m) x 3(n); warp = 32 rows x 64 cols.
//    B fragments hoisted to registers (tile-invariant weights): mainloop is
//    A-ldmatrix + HMMA only. Warp n-strips map 1:1 to outputs
//    (wn0->gtop, wn1->gbot, wn2->lin).
// ---------------------------------------------------------------------------
#define WS_STRIDE 200
#define XS_STRIDE 72
#define STG_STRIDE 72
#define WS_BYTES   (64 * WS_STRIDE * 2)          // 25600
#define XS_OFF     WS_BYTES
#define XS_BUF_BYTES (128 * XS_STRIDE * 2)       // 18432
#define STG_OFF    (XS_OFF + 2 * XS_BUF_BYTES)   // 62464
#define SG_GT_OFF  STG_OFF
#define SG_GB_OFF  (STG_OFF + 128 * STG_STRIDE * 2)
#define SG_LN_OFF  (STG_OFF + 2 * 128 * STG_STRIDE * 2)
#define BIAS_OFF   (STG_OFF + 3 * 128 * STG_STRIDE * 2)
#define PROJ_SMEM  (BIAS_OFF + 512)

static __device__ __forceinline__ void prefetch_tile(int tile, int buf, int tid,
                                                     uint32_t xs_base_u) {
    int n0 = tile * 128;
    for (int idx = tid; idx < 1024; idx += PROJ_T) {
        int r = idx >> 3, grp = idx & 7;
        int node = n0 + r;
        int node_c = node < N_ATOMS ? node : N_ATOMS - 1;
        uint32_t dst = xs_base_u + buf * XS_BUF_BYTES + (r * XS_STRIDE + grp * 8) * 2;
        const void* src = g_xh + (size_t)node_c * HID + grp * 8;
        int sz = (node < N_ATOMS) ? 16 : 0;
        asm volatile("cp.async.cg.shared.global [%0], [%1], 16, %2;"
                     :: "r"(dst), "l"(src), "r"(sz));
    }
    asm volatile("cp.async.commit_group;");
}

__global__ void __launch_bounds__(PROJ_T) proj_kernel(int layer,
                                                      const float* __restrict__ bg,
                                                      const float* __restrict__ bl) {
    extern __shared__ __align__(16) char smraw[];
    __half* ws    = (__half*)smraw;                   // [64][200]
    __half* sg_gt = (__half*)(smraw + SG_GT_OFF);     // [128][72]
    __half* sg_gb = (__half*)(smraw + SG_GB_OFF);     // [128][72]
    __half* sg_ln = (__half*)(smraw + SG_LN_OFF);     // [128][72]
    float*  bgs   = (float*)(smraw + BIAS_OFF);
    float*  bls   = bgs + 64;

    const int tid = threadIdx.x;
    const __half* wf = g_wf + layer * 64 * 192;

    for (int i = tid; i < 1536; i += PROJ_T) {
        int k = i / 24, grp = i - k * 24;
        *reinterpret_cast<uint4*>(ws + k * WS_STRIDE + grp * 8) =
            *reinterpret_cast<const uint4*>(wf + k * 192 + grp * 8);
    }
    if (tid < 64) { bgs[tid] = bg[tid]; bls[tid] = bl[tid]; }

    const uint32_t xs_base_u = cvta_s(smraw + XS_OFF);
    const uint32_t ws_u = cvta_s(ws);

    const int wid = tid >> 5, l = tid & 31;
    const int wm = wid & 3;    // rows wm*32 .. +31
    const int wn = wid >> 2;   // col strip: wn*64 .. +63 (0=gtop,1=gbot,2=lin)
    const int qid = l >> 2, tig = l & 3;

    __syncthreads();   // ws ready

    // Hoist B fragments: 8 n-frags x 4 k-steps, loaded once.
    // x4 trans: lanes 0-7 rows k0-7 @col c, 8-15 rows k8-15 @c, 16-23 k0-7 @c+8,
    // 24-31 k8-15 @c+8  ->  {r0,r1} = n-frag(c), {r2,r3} = n-frag(c+8).
    uint32_t breg[4][8][2];
    {
        const uint32_t bb = ws_u + ((l & 15) * WS_STRIDE + wn * 64 + (l >> 4) * 8) * 2;
        #pragma unroll
        for (int kk = 0; kk < 4; kk++) {
            #pragma unroll
            for (int nj = 0; nj < 4; nj++) {
                uint32_t r0, r1, r2, r3;
                asm volatile("ldmatrix.sync.aligned.m8n8.x4.trans.shared.b16 {%0,%1,%2,%3}, [%4];"
                             : "=r"(r0), "=r"(r1), "=r"(r2), "=r"(r3)
                             : "r"(bb + (kk * 16 * WS_STRIDE + nj * 16) * 2));
                breg[kk][2 * nj][0] = r0; breg[kk][2 * nj][1] = r1;
                breg[kk][2 * nj + 1][0] = r2; breg[kk][2 * nj + 1][1] = r3;
            }
        }
    }

    int t = blockIdx.x;
    int buf = 0;
    if (t < NTILES) prefetch_tile(t, 0, tid, xs_base_u);

    while (t < NTILES) {
        int tn = t + PROJ_GRID;
        asm volatile("cp.async.wait_group 0;");
        __syncthreads();   // A tile visible; prev staging reads done

        float acc[2][8][4];
        #pragma unroll
        for (int mi = 0; mi < 2; mi++)
            #pragma unroll
            for (int ni = 0; ni < 8; ni++)
                #pragma unroll
                for (int q = 0; q < 4; q++) acc[mi][ni][q] = 0.0f;

        const uint32_t a_base = xs_base_u + buf * XS_BUF_BYTES +
                                ((wm * 32 + (l & 15)) * XS_STRIDE + (l >> 4) * 8) * 2;
        #pragma unroll
        for (int kk = 0; kk < 4; kk++) {
            uint32_t astep = a_base + kk * 16 * 2;
            #pragma unroll
            for (int mi = 0; mi < 2; mi++) {
                uint32_t a0, a1, a2, a3;
                asm volatile("ldmatrix.sync.aligned.m8n8.x4.shared.b16 {%0,%1,%2,%3}, [%4];"
                             : "=r"(a0), "=r"(a1), "=r"(a2), "=r"(a3)
                             : "r"(astep + mi * 16 * XS_STRIDE * 2));
                #pragma unroll
                for (int ni = 0; ni < 8; ni++) {
                    asm volatile(
                        "mma.sync.aligned.m16n8k16.row.col.f32.f16.f16.f32 "
                        "{%0,%1,%2,%3},{%4,%5,%6,%7},{%8,%9},{%0,%1,%2,%3};"
                        : "+f"(acc[mi][ni][0]), "+f"(acc[mi][ni][1]),
                          "+f"(acc[mi][ni][2]), "+f"(acc[mi][ni][3])
                        : "r"(a0), "r"(a1), "r"(a2), "r"(a3),
                          "r"(breg[kk][ni][0]), "r"(breg[kk][ni][1]));
                }
            }
        }

        if (tn < NTILES) prefetch_tile(tn, buf ^ 1, tid, xs_base_u);

        // Stage fragments. Whole warp strip goes to one output kind.
        #pragma unroll
        for (int mi = 0; mi < 2; mi++) {
            int r0 = wm * 32 + mi * 16 + qid;
            int r1 = r0 + 8;
            #pragma unroll
            for (int ni = 0; ni < 8; ni++) {
                int cl = ni * 8 + tig * 2;   // 0..63 within strip
                float d0 = acc[mi][ni][0], d1 = acc[mi][ni][1];
                float d2 = acc[mi][ni][2], d3 = acc[mi][ni][3];
                if (wn == 0) {
                    float b0v = bgs[cl], b1v = bgs[cl + 1];
                    *reinterpret_cast<__half2*>(sg_gt + r0 * STG_STRIDE + cl) =
                        __floats2half2_rn(0.5f * (d0 + b0v), 0.5f * (d1 + b1v));
                    *reinterpret_cast<__half2*>(sg_gt + r1 * STG_STRIDE + cl) =
                        __floats2half2_rn(0.5f * (d2 + b0v), 0.5f * (d3 + b1v));
                } else if (wn == 1) {
                    *reinterpret_cast<__half2*>(sg_gb + r0 * STG_STRIDE + cl) =
                        __floats2half2_rn(0.5f * d0, 0.5f * d1);
                    *reinterpret_cast<__half2*>(sg_gb + r1 * STG_STRIDE + cl) =
                        __floats2half2_rn(0.5f * d2, 0.5f * d3);
                } else {
                    float b0v = bls[cl], b1v = bls[cl + 1];
                    *reinterpret_cast<__half2*>(sg_ln + r0 * STG_STRIDE + cl) =
                        __floats2half2_rn(d0 + b0v, d1 + b1v);
                    *reinterpret_cast<__half2*>(sg_ln + r1 * STG_STRIDE + cl) =
                        __floats2half2_rn(d2 + b0v, d3 + b1v);
                }
            }
        }
        __syncthreads();

        const int node0 = t * 128;
        // gtop write-out: 1024 uint4 chunks
        for (int cidx = tid; cidx < 1024; cidx += PROJ_T) {
            int r = cidx >> 3, grp = cidx & 7;
            int node = node0 + r;
            if (node < N_ATOMS) {
                uint4 vt = *reinterpret_cast<uint4*>(sg_gt + r * STG_STRIDE + grp * 8);
                *reinterpret_cast<uint4*>(g_gtop + (size_t)node * HID + grp * 8) = vt;
            }
        }
        // interleaved {gbot, linh} write-out as STG.128: 2048 uint4 chunks
        for (int cidx = tid; cidx < 2048; cidx += PROJ_T) {
            int r = cidx >> 4, pr = cidx & 15;   // pr = lane-pair (cols 4pr..4pr+3)
            int node = node0 + r;
            if (node < N_ATOMS) {
                uint4 v;
                v.x = *reinterpret_cast<uint32_t*>(sg_gb + r * STG_STRIDE + 4 * pr);
                v.y = *reinterpret_cast<uint32_t*>(sg_ln + r * STG_STRIDE + 4 * pr);
                v.z = *reinterpret_cast<uint32_t*>(sg_gb + r * STG_STRIDE + 4 * pr + 2);
                v.w = *reinterpret_cast<uint32_t*>(sg_ln + r * STG_STRIDE + 4 * pr + 2);
                *reinterpret_cast<uint4*>(g_gl + (size_t)node * 32 + 2 * pr) = v;
            }
        }

        t = tn;
        buf ^= 1;
    }
}

// ---------------------------------------------------------------------------
// 4. Gather-aggregate + fused node update.
// ---------------------------------------------------------------------------
__global__ void __launch_bounds__(256) gather_kernel() {
    int w = (blockIdx.x * 256 + threadIdx.x) >> 5;
    int l = threadIdx.x & 31;
    if (w >= N_ATOMS) return;

    int beg = __ldg(&g_off[w]);
    int end = __ldg(&g_off[w + 1]);

    __half2 gt = reinterpret_cast<const __half2*>(g_gtop)[(size_t)w * 32 + l];
    uint2 self = __ldg(&g_gl[(size_t)w * 32 + l]);
    float2 acc = __half22float2(*reinterpret_cast<__half2*>(&self.y));

    for (int base = beg; base < end; base += 32) {
        int myc = (base + l < end) ? g_scol[base + l] : 0;
        int m = min(32, end - base);
        #pragma unroll 4
        for (int j = 0; j < m; j++) {
            int cc = __shfl_sync(0xffffffffu, myc, j);
            uint2 v = __ldg(&g_gl[(size_t)cc * 32 + l]);
            __half2 gb = *reinterpret_cast<__half2*>(&v.x);
            __half2 lh = *reinterpret_cast<__half2*>(&v.y);
            __half2 pre = __hadd2(gt, gb);
            uint32_t th_u;
            asm("tanh.approx.f16x2 %0, %1;"
                : "=r"(th_u) : "r"(*reinterpret_cast<uint32_t*>(&pre)));
            __half2 th = *reinterpret_cast<__half2*>(&th_u);
            __half2 msg = __hfma2(th, lh, lh);       // (tanh+1)*linh, fp16
            float2 mf = __half22float2(msg);
            acc.x += 0.5f * mf.x;                    // FFMA-imm
            acc.y += 0.5f * mf.y;
        }
    }

    __half2* xo = reinterpret_cast<__half2*>(g_xh);
    xo[(size_t)w * 32 + l] = __floats2half2_rn(fmaxf(acc.x, 0.0f), fmaxf(acc.y, 0.0f));
}

// ---------------------------------------------------------------------------
// 5. Mean pool (grid=512)
// ---------------------------------------------------------------------------
__global__ void __launch_bounds__(256) pool_kernel() {
    int t = threadIdx.x;
    int col = t & 63;
    int grp = t >> 6;
    float acc = 0.0f;
    for (int node = blockIdx.x * 4 + grp; node < N_ATOMS; node += gridDim.x * 4)
        acc += __half2float(g_xh[(size_t)node * HID + col]);
    __shared__ float s[256];
    s[t] = acc;
    __syncthreads();
    if (grp == 0)
        atomicAdd(&g_pooled[col], s[col] + s[col + 64] + s[col + 128] + s[col + 192]);
}

// ---------------------------------------------------------------------------
// 6. MLP head
// ---------------------------------------------------------------------------
__global__ void head_kernel(const float* __restrict__ W1, const float* __restrict__ b1,
                            const float* __restrict__ W2, const float* __restrict__ b2,
                            float* __restrict__ out) {
    __shared__ float sp[64], sh[64];
    int t = threadIdx.x;
    if (t < 64) sp[t] = g_pooled[t] * (1.0f / (float)N_ATOMS);
    __syncthreads();
    if (t < 64) {
        float a = b1[t];
        #pragma unroll
        for (int k = 0; k < 64; k++) a += sp[k] * W1[k * 64 + t];
        sh[t] = fmaxf(a, 0.0f);
    }
    __syncthreads();
    if (t < 128) {
        float a = b2[t];
        #pragma unroll
        for (int k = 0; k < 64; k++) a += sh[k] * W2[k * 128 + t];
        out[t] = a;
    }
}

// ---------------------------------------------------------------------------
static cudaStream_t g_s1 = nullptr;
static cudaEvent_t  g_evF = nullptr, g_evJ = nullptr;
static int g_init = 0;

extern "C" void kernel_launch(void* const* d_in, const int* in_sizes, int n_in,
                              void* d_out, int out_size) {
    const int*   an  = (const int*)d_in[0];
    const int*   ei  = (const int*)d_in[3];
    const float* emb = (const float*)d_in[4];
    const float* Wl  = (const float*)d_in[5];
    const float* bl  = (const float*)d_in[6];
    const float* Wg  = (const float*)d_in[7];
    const float* bg  = (const float*)d_in[8];
    const float* W1  = (const float*)d_in[9];
    const float* b1  = (const float*)d_in[10];
    const float* W2  = (const float*)d_in[11];
    const float* b2  = (const float*)d_in[12];
    float* out = (float*)d_out;

    if (!g_init) {
        g_init = 1;
        if (cudaStreamCreateWithFlags(&g_s1, cudaStreamNonBlocking) != cudaSuccess) g_s1 = nullptr;
        if (g_s1) {
            cudaEventCreateWithFlags(&g_evF, cudaEventDisableTiming);
            cudaEventCreateWithFlags(&g_evJ, cudaEventDisableTiming);
        }
        cudaFuncSetAttribute(proj_kernel, cudaFuncAttributeMaxDynamicSharedMemorySize, PROJ_SMEM);
    }

    const int nodeElemBlocks = (N_ATOMS * HID + 255) / 256;   // 25000 (covers hist too)
    const int edgeBlocks = (N_EDGES + 255) / 256;             // 3907
    const int gatherBlocks = (N_ATOMS * 32 + 255) / 256;      // 12500
    const bool fork = (g_s1 != nullptr);
    cudaStream_t s1 = fork ? g_s1 : (cudaStream_t)0;

    wconv_kernel<<<400, 256>>>(Wg, Wl);                       // zeros g_cnt/pooled
    embed_kernel<<<nodeElemBlocks, 256>>>(an, emb, ei);       // xh + hist

    if (fork) {
        cudaEventRecord(g_evF, 0);
        cudaStreamWaitEvent(s1, g_evF, 0);
    }
    // sort chain on side stream; overlaps proj0
    scan_a_kernel<<<SCAN_NB, SCAN_T, 0, s1>>>();
    scan_c_kernel<<<SCAN_NB, SCAN_T, 0, s1>>>();
    scatter_kernel<<<edgeBlocks, 256, 0, s1>>>(ei);
    if (fork) cudaEventRecord(g_evJ, s1);

    proj_kernel<<<PROJ_GRID, PROJ_T, PROJ_SMEM>>>(0, bg, bl); // main stream

    if (fork) cudaStreamWaitEvent(0, g_evJ, 0);
    gather_kernel<<<gatherBlocks, 256>>>();

    for (int l = 1; l < 3; l++) {
        proj_kernel<<<PROJ_GRID, PROJ_T, PROJ_SMEM>>>(l, bg + l * 64, bl + l * 64);
        gather_kernel<<<gatherBlocks, 256>>>();
    }
    pool_kernel<<<512, 256>>>();
    head_kernel<<<1, 128>>>(W1, b1, W2, b2, out);
}

// round 14
// speedup vs baseline: 1.0076x; 1.0076x over previous
#include <cuda_runtime.h>
#include <cuda_fp16.h>
#include <cstdint>

// Problem constants
#define N_ATOMS 100000
#define N_EDGES 1000000
#define HID 64
#define OUTD 128
#define NTILES 782           // ceil(N_ATOMS / 128)
#define PROJ_GRID 148

#define SCAN_T 512
#define SCAN_ITEMS (N_ATOMS + 1)
#define SCAN_NB ((SCAN_ITEMS + SCAN_T - 1) / SCAN_T)

// Scratch (device globals: allocation-free rule)
__device__ __half g_xh[N_ATOMS * HID];         // node features, fp16 (MMA A operand)
__device__ __half g_gtop[N_ATOMS * HID];       // 0.5*(x @ Wg_top + b_gate)
__device__ unsigned short g_gb8[N_ATOMS * 32]; // 0.5*gbot as e4m3x2 per (node,lane)
__device__ uint32_t g_lh[N_ATOMS * 32];        // linh half2 per (node,lane)
__device__ __half g_wf[3 * 64 * 192];          // fused fp16 weights per layer
__device__ float  g_pooled[HID];

// Edge CSR (built per launch by counting sort)
__device__ int g_cnt[SCAN_ITEMS];
__device__ int g_off[SCAN_ITEMS];
__device__ int g_cur[N_ATOMS];
__device__ int g_part[SCAN_NB];
__device__ int g_scol[N_EDGES];

static __device__ __forceinline__ uint32_t cvta_s(const void* p) {
    uint32_t r;
    asm("{ .reg .u64 t; cvta.to.shared.u64 t, %1; cvt.u32.u64 %0, t; }" : "=r"(r) : "l"(p));
    return r;
}

// ---------------------------------------------------------------------------
// 0. Weight preconvert + zero g_cnt/g_pooled (runs FIRST)
// ---------------------------------------------------------------------------
__global__ void __launch_bounds__(256) wconv_kernel(const float* __restrict__ Wg,
                                                    const float* __restrict__ Wl) {
    int i = blockIdx.x * 256 + threadIdx.x;
    if (i < 3 * 64 * 192) {
        int lay = i / (64 * 192);
        int rem = i - lay * (64 * 192);
        int k = rem / 192, c = rem - k * 192;
        float w;
        if (c < 64)       w = Wg[lay * 128 * 64 + k * 64 + c];
        else if (c < 128) w = Wg[lay * 128 * 64 + (64 + k) * 64 + (c - 64)];
        else              w = Wl[lay * 64 * 64 + k * 64 + (c - 128)];
        g_wf[i] = __float2half(w);
    }
    if (i < SCAN_ITEMS) g_cnt[i] = 0;
    if (i < HID) g_pooled[i] = 0.0f;
}

// ---------------------------------------------------------------------------
// 1. Embedding lookup + edge histogram
// ---------------------------------------------------------------------------
__global__ void __launch_bounds__(256) embed_kernel(const int* __restrict__ an,
                                                    const float* __restrict__ emb,
                                                    const int* __restrict__ ei) {
    int i = blockIdx.x * 256 + threadIdx.x;
    if (i < N_ATOMS * HID) {
        int v = i >> 6;
        g_xh[i] = __float2half(emb[an[v] * HID + (i & 63)]);
    }
    if (i < N_EDGES) atomicAdd(&g_cnt[ei[i]], 1);
}

// ---------------------------------------------------------------------------
// 2. Scan + scatter (counting sort by row)
// ---------------------------------------------------------------------------
__global__ void __launch_bounds__(SCAN_T) scan_a_kernel() {
    __shared__ int s[SCAN_T];
    int t = threadIdx.x;
    int i = blockIdx.x * SCAN_T + t;
    s[t] = (i < SCAN_ITEMS) ? g_cnt[i] : 0;
    __syncthreads();
    for (int d = SCAN_T / 2; d > 0; d >>= 1) {
        if (t < d) s[t] += s[t + d];
        __syncthreads();
    }
    if (t == 0) g_part[blockIdx.x] = s[0];
}

__global__ void __launch_bounds__(SCAN_T) scan_c_kernel() {
    __shared__ int s[SCAN_T];
    __shared__ int p[256];
    int t = threadIdx.x;
    int i = blockIdx.x * SCAN_T + t;

    if (t < 256) p[t] = (t < SCAN_NB) ? g_part[t] : 0;
    __syncthreads();
    for (int d = 1; d < 256; d <<= 1) {
        int a = 0;
        if (t < 256 && t >= d) a = p[t - d];
        __syncthreads();
        if (t < 256) p[t] += a;
        __syncthreads();
    }
    int prefix = (blockIdx.x == 0) ? 0 : p[blockIdx.x - 1];

    int v = (i < SCAN_ITEMS) ? g_cnt[i] : 0;
    s[t] = v;
    __syncthreads();
    for (int d = 1; d < SCAN_T; d <<= 1) {
        int a = (t >= d) ? s[t - d] : 0;
        __syncthreads();
        s[t] += a;
        __syncthreads();
    }
    int off = prefix + s[t] - v;  // exclusive
    if (i < SCAN_ITEMS) g_off[i] = off;
    if (i < N_ATOMS)    g_cur[i] = off;
}

__global__ void __launch_bounds__(256) scatter_kernel(const int* __restrict__ ei) {
    int e = blockIdx.x * 256 + threadIdx.x;
    if (e < N_EDGES) {
        int r = ei[e];
        int c = ei[N_EDGES + e];
        int p = atomicAdd(&g_cur[r], 1);
        g_scol[p] = c;
    }
}

// ---------------------------------------------------------------------------
// 3. Persistent tensor-core projection (r12-proven: 512 thr, 16 warps 4x4,
//    cp.async double-buffered). Outputs: gtop fp16, gbot e4m3, linh fp16.
// ---------------------------------------------------------------------------
#define WS_STRIDE 200
#define XS_STRIDE 72
#define STG_STRIDE 72
#define WS_BYTES   (64 * WS_STRIDE * 2)          // 25600
#define XS_OFF     WS_BYTES
#define XS_BUF_BYTES (128 * XS_STRIDE * 2)       // 18432
#define STG_OFF    (XS_OFF + 2 * XS_BUF_BYTES)   // 62464
#define SG_GT_OFF  STG_OFF
#define SG_GB_OFF  (STG_OFF + 128 * STG_STRIDE * 2)
#define SG_LN_OFF  (STG_OFF + 2 * 128 * STG_STRIDE * 2)
#define BIAS_OFF   (STG_OFF + 3 * 128 * STG_STRIDE * 2)
#define PROJ_SMEM  (BIAS_OFF + 512)

static __device__ __forceinline__ void prefetch_tile(int tile, int buf, int tid,
                                                     uint32_t xs_base_u) {
    int n0 = tile * 128;
    #pragma unroll
    for (int p = 0; p < 2; p++) {
        int idx = tid + p * 512;
        int r = idx >> 3, grp = idx & 7;
        int node = n0 + r;
        int node_c = node < N_ATOMS ? node : N_ATOMS - 1;
        uint32_t dst = xs_base_u + buf * XS_BUF_BYTES + (r * XS_STRIDE + grp * 8) * 2;
        const void* src = g_xh + (size_t)node_c * HID + grp * 8;
        int sz = (node < N_ATOMS) ? 16 : 0;
        asm volatile("cp.async.cg.shared.global [%0], [%1], 16, %2;"
                     :: "r"(dst), "l"(src), "r"(sz));
    }
    asm volatile("cp.async.commit_group;");
}

__global__ void __launch_bounds__(512) proj_kernel(int layer,
                                                   const float* __restrict__ bg,
                                                   const float* __restrict__ bl) {
    extern __shared__ __align__(16) char smraw[];
    __half* ws    = (__half*)smraw;                   // [64][200]
    __half* sg_gt = (__half*)(smraw + SG_GT_OFF);     // [128][72]
    __half* sg_gb = (__half*)(smraw + SG_GB_OFF);     // [128][72]
    __half* sg_ln = (__half*)(smraw + SG_LN_OFF);     // [128][72]
    float*  bgs   = (float*)(smraw + BIAS_OFF);
    float*  bls   = bgs + 64;

    const int tid = threadIdx.x;
    const __half* wf = g_wf + layer * 64 * 192;

    for (int i = tid; i < 1536; i += 512) {
        int k = i / 24, grp = i - k * 24;
        *reinterpret_cast<uint4*>(ws + k * WS_STRIDE + grp * 8) =
            *reinterpret_cast<const uint4*>(wf + k * 192 + grp * 8);
    }
    if (tid < 64) { bgs[tid] = bg[tid]; bls[tid] = bl[tid]; }

    const uint32_t xs_base_u = cvta_s(smraw + XS_OFF);
    const uint32_t ws_u = cvta_s(ws);

    const int wid = tid >> 5, l = tid & 31;
    const int wm = wid & 3;    // rows wm*32 .. +31
    const int wn = wid >> 2;   // cols wn*48 .. +47
    const uint32_t b_base = ws_u + ((l & 15) * WS_STRIDE + wn * 48) * 2;
    const int qid = l >> 2, tig = l & 3;

    int t = blockIdx.x;
    int buf = 0;
    if (t < NTILES) prefetch_tile(t, 0, tid, xs_base_u);

    while (t < NTILES) {
        int tn = t + PROJ_GRID;
        asm volatile("cp.async.wait_group 0;");
        __syncthreads();

        float acc[2][6][4];
        #pragma unroll
        for (int mi = 0; mi < 2; mi++)
            #pragma unroll
            for (int ni = 0; ni < 6; ni++)
                #pragma unroll
                for (int q = 0; q < 4; q++) acc[mi][ni][q] = 0.0f;

        const uint32_t a_base = xs_base_u + buf * XS_BUF_BYTES +
                                ((wm * 32 + (l & 15)) * XS_STRIDE + (l >> 4) * 8) * 2;
        #pragma unroll
        for (int kk = 0; kk < 4; kk++) {
            uint32_t b[6][2];
            uint32_t bstep = b_base + kk * 16 * WS_STRIDE * 2;
            #pragma unroll
            for (int ni = 0; ni < 6; ni++) {
                asm volatile("ldmatrix.sync.aligned.m8n8.x2.trans.shared.b16 {%0,%1}, [%2];"
                             : "=r"(b[ni][0]), "=r"(b[ni][1]) : "r"(bstep + ni * 8 * 2));
            }
            uint32_t astep = a_base + kk * 16 * 2;
            #pragma unroll
            for (int mi = 0; mi < 2; mi++) {
                uint32_t a0, a1, a2, a3;
                asm volatile("ldmatrix.sync.aligned.m8n8.x4.shared.b16 {%0,%1,%2,%3}, [%4];"
                             : "=r"(a0), "=r"(a1), "=r"(a2), "=r"(a3)
                             : "r"(astep + mi * 16 * XS_STRIDE * 2));
                #pragma unroll
                for (int ni = 0; ni < 6; ni++) {
                    asm volatile(
                        "mma.sync.aligned.m16n8k16.row.col.f32.f16.f16.f32 "
                        "{%0,%1,%2,%3},{%4,%5,%6,%7},{%8,%9},{%0,%1,%2,%3};"
                        : "+f"(acc[mi][ni][0]), "+f"(acc[mi][ni][1]),
                          "+f"(acc[mi][ni][2]), "+f"(acc[mi][ni][3])
                        : "r"(a0), "r"(a1), "r"(a2), "r"(a3), "r"(b[ni][0]), "r"(b[ni][1]));
                }
            }
        }

        if (tn < NTILES) prefetch_tile(tn, buf ^ 1, tid, xs_base_u);

        // Stage fragments (fp16; gtop/gbot pre-scaled by 0.5 for f16x2 tanh)
        #pragma unroll
        for (int mi = 0; mi < 2; mi++) {
            int r0 = wm * 32 + mi * 16 + qid;
            int r1 = r0 + 8;
            #pragma unroll
            for (int ni = 0; ni < 6; ni++) {
                int c = wn * 48 + ni * 8 + tig * 2;
                float d0 = acc[mi][ni][0], d1 = acc[mi][ni][1];
                float d2 = acc[mi][ni][2], d3 = acc[mi][ni][3];
                if (c < 64) {
                    float b0v = bgs[c], b1v = bgs[c + 1];
                    *reinterpret_cast<__half2*>(sg_gt + r0 * STG_STRIDE + c) =
                        __floats2half2_rn(0.5f * (d0 + b0v), 0.5f * (d1 + b1v));
                    *reinterpret_cast<__half2*>(sg_gt + r1 * STG_STRIDE + c) =
                        __floats2half2_rn(0.5f * (d2 + b0v), 0.5f * (d3 + b1v));
                } else if (c < 128) {
                    int cc = c - 64;
                    *reinterpret_cast<__half2*>(sg_gb + r0 * STG_STRIDE + cc) =
                        __floats2half2_rn(0.5f * d0, 0.5f * d1);
                    *reinterpret_cast<__half2*>(sg_gb + r1 * STG_STRIDE + cc) =
                        __floats2half2_rn(0.5f * d2, 0.5f * d3);
                } else {
                    int cc = c - 128;
                    float b0v = bls[cc], b1v = bls[cc + 1];
                    *reinterpret_cast<__half2*>(sg_ln + r0 * STG_STRIDE + cc) =
                        __floats2half2_rn(d0 + b0v, d1 + b1v);
                    *reinterpret_cast<__half2*>(sg_ln + r1 * STG_STRIDE + cc) =
                        __floats2half2_rn(d2 + b0v, d3 + b1v);
                }
            }
        }
        __syncthreads();

        const int node0 = t * 128;
        // gtop write-out: 1024 uint4 chunks
        #pragma unroll
        for (int p = 0; p < 2; p++) {
            int cidx = tid + p * 512;
            int r = cidx >> 3, grp = cidx & 7;
            int node = node0 + r;
            if (node < N_ATOMS) {
                uint4 vt = *reinterpret_cast<uint4*>(sg_gt + r * STG_STRIDE + grp * 8);
                *reinterpret_cast<uint4*>(g_gtop + (size_t)node * HID + grp * 8) = vt;
            }
        }
        // linh write-out: 1024 uint4 chunks (direct copy)
        #pragma unroll
        for (int p = 0; p < 2; p++) {
            int cidx = tid + p * 512;
            int r = cidx >> 3, grp = cidx & 7;
            int node = node0 + r;
            if (node < N_ATOMS) {
                uint4 vl = *reinterpret_cast<uint4*>(sg_ln + r * STG_STRIDE + grp * 8);
                *reinterpret_cast<uint4*>(g_lh + (size_t)node * 32 + grp * 4) = vl;
            }
        }
        // gbot fp8 write-out: 512 uint4 chunks (8 half2 -> 8 e4m3x2 each)
        {
            int cidx = tid;              // exactly 512
            int r = cidx >> 2, q = cidx & 3;
            int node = node0 + r;
            if (node < N_ATOMS) {
                unsigned short o[8];
                #pragma unroll
                for (int j = 0; j < 8; j++) {
                    uint32_t hv = *reinterpret_cast<uint32_t*>(
                        sg_gb + r * STG_STRIDE + q * 16 + 2 * j);
                    asm("cvt.rn.satfinite.e4m3x2.f16x2 %0, %1;"
                        : "=h"(o[j]) : "r"(hv));
                }
                *reinterpret_cast<uint4*>(g_gb8 + (size_t)node * 32 + q * 8) =
                    *reinterpret_cast<uint4*>(o);
            }
        }

        t = tn;
        buf ^= 1;
    }
}

// ---------------------------------------------------------------------------
// 4. Gather-aggregate + fused node update.
//    gbot arrives as e4m3x2 (64B/edge); linh fp16 (128B/edge); gtop fp16.
// ---------------------------------------------------------------------------
__global__ void __launch_bounds__(256) gather_kernel() {
    int w = (blockIdx.x * 256 + threadIdx.x) >> 5;
    int l = threadIdx.x & 31;
    if (w >= N_ATOMS) return;

    int beg = __ldg(&g_off[w]);
    int end = __ldg(&g_off[w + 1]);

    __half2 gt = reinterpret_cast<const __half2*>(g_gtop)[(size_t)w * 32 + l];
    uint32_t selfu = __ldg(&g_lh[(size_t)w * 32 + l]);
    float2 acc = __half22float2(*reinterpret_cast<__half2*>(&selfu));

    for (int base = beg; base < end; base += 32) {
        int myc = (base + l < end) ? g_scol[base + l] : 0;
        int m = min(32, end - base);
        #pragma unroll 4
        for (int j = 0; j < m; j++) {
            int cc = __shfl_sync(0xffffffffu, myc, j);
            unsigned short gb8 = __ldg(&g_gb8[(size_t)cc * 32 + l]);
            uint32_t lhu = __ldg(&g_lh[(size_t)cc * 32 + l]);
            uint32_t gbu;
            asm("cvt.rn.f16x2.e4m3x2 %0, %1;" : "=r"(gbu) : "h"(gb8));
            __half2 gb = *reinterpret_cast<__half2*>(&gbu);
            __half2 lh = *reinterpret_cast<__half2*>(&lhu);
            __half2 pre = __hadd2(gt, gb);
            uint32_t th_u;
            asm("tanh.approx.f16x2 %0, %1;"
                : "=r"(th_u) : "r"(*reinterpret_cast<uint32_t*>(&pre)));
            __half2 th = *reinterpret_cast<__half2*>(&th_u);
            __half2 msg = __hfma2(th, lh, lh);       // (tanh+1)*linh, fp16
            float2 mf = __half22float2(msg);
            acc.x += 0.5f * mf.x;                    // FFMA-imm
            acc.y += 0.5f * mf.y;
        }
    }

    __half2* xo = reinterpret_cast<__half2*>(g_xh);
    xo[(size_t)w * 32 + l] = __floats2half2_rn(fmaxf(acc.x, 0.0f), fmaxf(acc.y, 0.0f));
}

// ---------------------------------------------------------------------------
// 5. Mean pool (grid=512)
// ---------------------------------------------------------------------------
__global__ void __launch_bounds__(256) pool_kernel() {
    int t = threadIdx.x;
    int col = t & 63;
    int grp = t >> 6;
    float acc = 0.0f;
    for (int node = blockIdx.x * 4 + grp; node < N_ATOMS; node += gridDim.x * 4)
        acc += __half2float(g_xh[(size_t)node * HID + col]);
    __shared__ float s[256];
    s[t] = acc;
    __syncthreads();
    if (grp == 0)
        atomicAdd(&g_pooled[col], s[col] + s[col + 64] + s[col + 128] + s[col + 192]);
}

// ---------------------------------------------------------------------------
// 6. MLP head
// ---------------------------------------------------------------------------
__global__ void head_kernel(const float* __restrict__ W1, const float* __restrict__ b1,
                            const float* __restrict__ W2, const float* __restrict__ b2,
                            float* __restrict__ out) {
    __shared__ float sp[64], sh[64];
    int t = threadIdx.x;
    if (t < 64) sp[t] = g_pooled[t] * (1.0f / (float)N_ATOMS);
    __syncthreads();
    if (t < 64) {
        float a = b1[t];
        #pragma unroll
        for (int k = 0; k < 64; k++) a += sp[k] * W1[k * 64 + t];
        sh[t] = fmaxf(a, 0.0f);
    }
    __syncthreads();
    if (t < 128) {
        float a = b2[t];
        #pragma unroll
        for (int k = 0; k < 64; k++) a += sh[k] * W2[k * 128 + t];
        out[t] = a;
    }
}

// ---------------------------------------------------------------------------
static cudaStream_t g_s1 = nullptr;
static cudaEvent_t  g_evF = nullptr, g_evJ = nullptr;
static int g_init = 0;

extern "C" void kernel_launch(void* const* d_in, const int* in_sizes, int n_in,
                              void* d_out, int out_size) {
    const int*   an  = (const int*)d_in[0];
    const int*   ei  = (const int*)d_in[3];
    const float* emb = (const float*)d_in[4];
    const float* Wl  = (const float*)d_in[5];
    const float* bl  = (const float*)d_in[6];
    const float* Wg  = (const float*)d_in[7];
    const float* bg  = (const float*)d_in[8];
    const float* W1  = (const float*)d_in[9];
    const float* b1  = (const float*)d_in[10];
    const float* W2  = (const float*)d_in[11];
    const float* b2  = (const float*)d_in[12];
    float* out = (float*)d_out;

    if (!g_init) {
        g_init = 1;
        if (cudaStreamCreateWithFlags(&g_s1, cudaStreamNonBlocking) != cudaSuccess) g_s1 = nullptr;
        if (g_s1) {
            cudaEventCreateWithFlags(&g_evF, cudaEventDisableTiming);
            cudaEventCreateWithFlags(&g_evJ, cudaEventDisableTiming);
        }
        cudaFuncSetAttribute(proj_kernel, cudaFuncAttributeMaxDynamicSharedMemorySize, PROJ_SMEM);
    }

    const int nodeElemBlocks = (N_ATOMS * HID + 255) / 256;   // 25000 (covers hist too)
    const int edgeBlocks = (N_EDGES + 255) / 256;             // 3907
    const int gatherBlocks = (N_ATOMS * 32 + 255) / 256;      // 12500
    const bool fork = (g_s1 != nullptr);
    cudaStream_t s1 = fork ? g_s1 : (cudaStream_t)0;

    wconv_kernel<<<400, 256>>>(Wg, Wl);                       // zeros g_cnt/pooled
    embed_kernel<<<nodeElemBlocks, 256>>>(an, emb, ei);       // xh + hist

    if (fork) {
        cudaEventRecord(g_evF, 0);
        cudaStreamWaitEvent(s1, g_evF, 0);
    }
    // sort chain on side stream; overlaps proj0
    scan_a_kernel<<<SCAN_NB, SCAN_T, 0, s1>>>();
    scan_c_kernel<<<SCAN_NB, SCAN_T, 0, s1>>>();
    scatter_kernel<<<edgeBlocks, 256, 0, s1>>>(ei);
    if (fork) cudaEventRecord(g_evJ, s1);

    proj_kernel<<<PROJ_GRID, 512, PROJ_SMEM>>>(0, bg, bl);    // main stream

    if (fork) cudaStreamWaitEvent(0, g_evJ, 0);
    gather_kernel<<<gatherBlocks, 256>>>();

    for (int l = 1; l < 3; l++) {
        proj_kernel<<<PROJ_GRID, 512, PROJ_SMEM>>>(l, bg + l * 64, bl + l * 64);
        gather_kernel<<<gatherBlocks, 256>>>();
    }
    pool_kernel<<<512, 256>>>();
    head_kernel<<<1, 128>>>(W1, b1, W2, b2, out);
}

// round 15
// speedup vs baseline: 1.0808x; 1.0727x over previous
#include <cuda_runtime.h>
#include <cuda_fp16.h>
#include <cstdint>

// Problem constants
#define N_ATOMS 100000
#define N_EDGES 1000000
#define HID 64
#define OUTD 128
#define NTILES 782           // ceil(N_ATOMS / 128)
#define PROJ_GRID 148

#define SCAN_T 512
#define SCAN_ITEMS (N_ATOMS + 1)
#define SCAN_NB ((SCAN_ITEMS + SCAN_T - 1) / SCAN_T)

// Scratch (device globals: allocation-free rule)
__device__ __half g_xh[N_ATOMS * HID];     // node features, fp16 (MMA A operand)
__device__ __half g_gtop[N_ATOMS * HID];   // 0.5*(x @ Wg_top + b_gate)
__device__ uint2  g_gl[N_ATOMS * 32];      // per (node,lane): {0.5*gbot half2, linh half2}
__device__ __half g_wf[3 * 64 * 192];      // fused fp16 weights per layer
__device__ float  g_pooled[HID];

// Edge CSR (built per launch by counting sort)
__device__ int g_cnt[SCAN_ITEMS];
__device__ int g_off[SCAN_ITEMS];
__device__ int g_cur[N_ATOMS];
__device__ int g_part[SCAN_NB];
__device__ int g_scol[N_EDGES];

static __device__ __forceinline__ uint32_t cvta_s(const void* p) {
    uint32_t r;
    asm("{ .reg .u64 t; cvta.to.shared.u64 t, %1; cvt.u32.u64 %0, t; }" : "=r"(r) : "l"(p));
    return r;
}

// ---------------------------------------------------------------------------
// 0. Weight preconvert + zero g_cnt/g_pooled (runs FIRST)
// ---------------------------------------------------------------------------
__global__ void __launch_bounds__(256) wconv_kernel(const float* __restrict__ Wg,
                                                    const float* __restrict__ Wl) {
    int i = blockIdx.x * 256 + threadIdx.x;
    if (i < 3 * 64 * 192) {
        int lay = i / (64 * 192);
        int rem = i - lay * (64 * 192);
        int k = rem / 192, c = rem - k * 192;
        float w;
        if (c < 64)       w = Wg[lay * 128 * 64 + k * 64 + c];
        else if (c < 128) w = Wg[lay * 128 * 64 + (64 + k) * 64 + (c - 64)];
        else              w = Wl[lay * 64 * 64 + k * 64 + (c - 128)];
        g_wf[i] = __float2half(w);
    }
    if (i < SCAN_ITEMS) g_cnt[i] = 0;
    if (i < HID) g_pooled[i] = 0.0f;
}

// ---------------------------------------------------------------------------
// 1. Embedding lookup (vectorized: 8 ch/thread, STG.128) + edge histogram
// ---------------------------------------------------------------------------
__global__ void __launch_bounds__(256) embed_kernel(const int* __restrict__ an,
                                                    const float* __restrict__ emb,
                                                    const int* __restrict__ ei) {
    int i = blockIdx.x * 256 + threadIdx.x;
    if (i < N_ATOMS * 8) {
        int v = i >> 3, ch = i & 7;
        const float4* e4 = reinterpret_cast<const float4*>(
            emb + (size_t)__ldg(&an[v]) * HID + ch * 8);
        float4 f0 = __ldg(&e4[0]), f1 = __ldg(&e4[1]);
        __half2 h[4];
        h[0] = __floats2half2_rn(f0.x, f0.y);
        h[1] = __floats2half2_rn(f0.z, f0.w);
        h[2] = __floats2half2_rn(f1.x, f1.y);
        h[3] = __floats2half2_rn(f1.z, f1.w);
        *reinterpret_cast<uint4*>(g_xh + (size_t)v * HID + ch * 8) =
            *reinterpret_cast<uint4*>(h);
    }
    if (i < N_EDGES) atomicAdd(&g_cnt[ei[i]], 1);
}

// ---------------------------------------------------------------------------
// 2. Scan (a: block sums; c: fused partial-scan + local scan) + scatter
// ---------------------------------------------------------------------------
__global__ void __launch_bounds__(SCAN_T) scan_a_kernel() {
    __shared__ int s[SCAN_T];
    int t = threadIdx.x;
    int i = blockIdx.x * SCAN_T + t;
    s[t] = (i < SCAN_ITEMS) ? g_cnt[i] : 0;
    __syncthreads();
    for (int d = SCAN_T / 2; d > 0; d >>= 1) {
        if (t < d) s[t] += s[t + d];
        __syncthreads();
    }
    if (t == 0) g_part[blockIdx.x] = s[0];
}

__global__ void __launch_bounds__(SCAN_T) scan_c_kernel() {
    __shared__ int s[SCAN_T];
    __shared__ int p[256];
    int t = threadIdx.x;
    int i = blockIdx.x * SCAN_T + t;

    if (t < 256) p[t] = (t < SCAN_NB) ? g_part[t] : 0;
    __syncthreads();
    for (int d = 1; d < 256; d <<= 1) {
        int a = 0;
        if (t < 256 && t >= d) a = p[t - d];
        __syncthreads();
        if (t < 256) p[t] += a;
        __syncthreads();
    }
    int prefix = (blockIdx.x == 0) ? 0 : p[blockIdx.x - 1];

    int v = (i < SCAN_ITEMS) ? g_cnt[i] : 0;
    s[t] = v;
    __syncthreads();
    for (int d = 1; d < SCAN_T; d <<= 1) {
        int a = (t >= d) ? s[t - d] : 0;
        __syncthreads();
        s[t] += a;
        __syncthreads();
    }
    int off = prefix + s[t] - v;  // exclusive
    if (i < SCAN_ITEMS) g_off[i] = off;
    if (i < N_ATOMS)    g_cur[i] = off;
}

__global__ void __launch_bounds__(256) scatter_kernel(const int* __restrict__ ei) {
    int e = blockIdx.x * 256 + threadIdx.x;
    if (e < N_EDGES) {
        int r = ei[e];
        int c = ei[N_EDGES + e];
        int p = atomicAdd(&g_cur[r], 1);
        g_scol[p] = c;
    }
}

// ---------------------------------------------------------------------------
// 3. Persistent tensor-core projection (r12-proven: 512 thr, 16 warps 4x4,
//    cp.async double-buffered; interleaved {gbot,linh} uint2 epilogue).
// ---------------------------------------------------------------------------
#define WS_STRIDE 200
#define XS_STRIDE 72
#define STG_STRIDE 72
#define WS_BYTES   (64 * WS_STRIDE * 2)          // 25600
#define XS_OFF     WS_BYTES
#define XS_BUF_BYTES (128 * XS_STRIDE * 2)       // 18432
#define STG_OFF    (XS_OFF + 2 * XS_BUF_BYTES)   // 62464
#define SG_GT_OFF  STG_OFF
#define SG_GB_OFF  (STG_OFF + 128 * STG_STRIDE * 2)
#define SG_LN_OFF  (STG_OFF + 2 * 128 * STG_STRIDE * 2)
#define BIAS_OFF   (STG_OFF + 3 * 128 * STG_STRIDE * 2)
#define PROJ_SMEM  (BIAS_OFF + 512)

static __device__ __forceinline__ void prefetch_tile(int tile, int buf, int tid,
                                                     uint32_t xs_base_u) {
    int n0 = tile * 128;
    #pragma unroll
    for (int p = 0; p < 2; p++) {
        int idx = tid + p * 512;
        int r = idx >> 3, grp = idx & 7;
        int node = n0 + r;
        int node_c = node < N_ATOMS ? node : N_ATOMS - 1;
        uint32_t dst = xs_base_u + buf * XS_BUF_BYTES + (r * XS_STRIDE + grp * 8) * 2;
        const void* src = g_xh + (size_t)node_c * HID + grp * 8;
        int sz = (node < N_ATOMS) ? 16 : 0;
        asm volatile("cp.async.cg.shared.global [%0], [%1], 16, %2;"
                     :: "r"(dst), "l"(src), "r"(sz));
    }
    asm volatile("cp.async.commit_group;");
}

__global__ void __launch_bounds__(512) proj_kernel(int layer,
                                                   const float* __restrict__ bg,
                                                   const float* __restrict__ bl) {
    extern __shared__ __align__(16) char smraw[];
    __half* ws    = (__half*)smraw;                   // [64][200]
    __half* sg_gt = (__half*)(smraw + SG_GT_OFF);     // [128][72]
    __half* sg_gb = (__half*)(smraw + SG_GB_OFF);     // [128][72]
    __half* sg_ln = (__half*)(smraw + SG_LN_OFF);     // [128][72]
    float*  bgs   = (float*)(smraw + BIAS_OFF);
    float*  bls   = bgs + 64;

    const int tid = threadIdx.x;
    const __half* wf = g_wf + layer * 64 * 192;

    for (int i = tid; i < 1536; i += 512) {
        int k = i / 24, grp = i - k * 24;
        *reinterpret_cast<uint4*>(ws + k * WS_STRIDE + grp * 8) =
            *reinterpret_cast<const uint4*>(wf + k * 192 + grp * 8);
    }
    if (tid < 64) { bgs[tid] = bg[tid]; bls[tid] = bl[tid]; }

    const uint32_t xs_base_u = cvta_s(smraw + XS_OFF);
    const uint32_t ws_u = cvta_s(ws);

    const int wid = tid >> 5, l = tid & 31;
    const int wm = wid & 3;    // rows wm*32 .. +31
    const int wn = wid >> 2;   // cols wn*48 .. +47
    const uint32_t b_base = ws_u + ((l & 15) * WS_STRIDE + wn * 48) * 2;
    const int qid = l >> 2, tig = l & 3;

    int t = blockIdx.x;
    int buf = 0;
    if (t < NTILES) prefetch_tile(t, 0, tid, xs_base_u);

    while (t < NTILES) {
        int tn = t + PROJ_GRID;
        asm volatile("cp.async.wait_group 0;");
        __syncthreads();

        float acc[2][6][4];
        #pragma unroll
        for (int mi = 0; mi < 2; mi++)
            #pragma unroll
            for (int ni = 0; ni < 6; ni++)
                #pragma unroll
                for (int q = 0; q < 4; q++) acc[mi][ni][q] = 0.0f;

        const uint32_t a_base = xs_base_u + buf * XS_BUF_BYTES +
                                ((wm * 32 + (l & 15)) * XS_STRIDE + (l >> 4) * 8) * 2;
        #pragma unroll
        for (int kk = 0; kk < 4; kk++) {
            uint32_t b[6][2];
            uint32_t bstep = b_base + kk * 16 * WS_STRIDE * 2;
            #pragma unroll
            for (int ni = 0; ni < 6; ni++) {
                asm volatile("ldmatrix.sync.aligned.m8n8.x2.trans.shared.b16 {%0,%1}, [%2];"
                             : "=r"(b[ni][0]), "=r"(b[ni][1]) : "r"(bstep + ni * 8 * 2));
            }
            uint32_t astep = a_base + kk * 16 * 2;
            #pragma unroll
            for (int mi = 0; mi < 2; mi++) {
                uint32_t a0, a1, a2, a3;
                asm volatile("ldmatrix.sync.aligned.m8n8.x4.shared.b16 {%0,%1,%2,%3}, [%4];"
                             : "=r"(a0), "=r"(a1), "=r"(a2), "=r"(a3)
                             : "r"(astep + mi * 16 * XS_STRIDE * 2));
                #pragma unroll
                for (int ni = 0; ni < 6; ni++) {
                    asm volatile(
                        "mma.sync.aligned.m16n8k16.row.col.f32.f16.f16.f32 "
                        "{%0,%1,%2,%3},{%4,%5,%6,%7},{%8,%9},{%0,%1,%2,%3};"
                        : "+f"(acc[mi][ni][0]), "+f"(acc[mi][ni][1]),
                          "+f"(acc[mi][ni][2]), "+f"(acc[mi][ni][3])
                        : "r"(a0), "r"(a1), "r"(a2), "r"(a3), "r"(b[ni][0]), "r"(b[ni][1]));
                }
            }
        }

        if (tn < NTILES) prefetch_tile(tn, buf ^ 1, tid, xs_base_u);

        // Stage fragments (fp16; gtop/gbot pre-scaled by 0.5 for f16x2 tanh)
        #pragma unroll
        for (int mi = 0; mi < 2; mi++) {
            int r0 = wm * 32 + mi * 16 + qid;
            int r1 = r0 + 8;
            #pragma unroll
            for (int ni = 0; ni < 6; ni++) {
                int c = wn * 48 + ni * 8 + tig * 2;
                float d0 = acc[mi][ni][0], d1 = acc[mi][ni][1];
                float d2 = acc[mi][ni][2], d3 = acc[mi][ni][3];
                if (c < 64) {
                    float b0v = bgs[c], b1v = bgs[c + 1];
                    *reinterpret_cast<__half2*>(sg_gt + r0 * STG_STRIDE + c) =
                        __floats2half2_rn(0.5f * (d0 + b0v), 0.5f * (d1 + b1v));
                    *reinterpret_cast<__half2*>(sg_gt + r1 * STG_STRIDE + c) =
                        __floats2half2_rn(0.5f * (d2 + b0v), 0.5f * (d3 + b1v));
                } else if (c < 128) {
                    int cc = c - 64;
                    *reinterpret_cast<__half2*>(sg_gb + r0 * STG_STRIDE + cc) =
                        __floats2half2_rn(0.5f * d0, 0.5f * d1);
                    *reinterpret_cast<__half2*>(sg_gb + r1 * STG_STRIDE + cc) =
                        __floats2half2_rn(0.5f * d2, 0.5f * d3);
                } else {
                    int cc = c - 128;
                    float b0v = bls[cc], b1v = bls[cc + 1];
                    *reinterpret_cast<__half2*>(sg_ln + r0 * STG_STRIDE + cc) =
                        __floats2half2_rn(d0 + b0v, d1 + b1v);
                    *reinterpret_cast<__half2*>(sg_ln + r1 * STG_STRIDE + cc) =
                        __floats2half2_rn(d2 + b0v, d3 + b1v);
                }
            }
        }
        __syncthreads();

        const int node0 = t * 128;
        #pragma unroll
        for (int p = 0; p < 2; p++) {
            int cidx = tid + p * 512;
            int r = cidx >> 3, grp = cidx & 7;
            int node = node0 + r;
            if (node < N_ATOMS) {
                uint4 vt = *reinterpret_cast<uint4*>(sg_gt + r * STG_STRIDE + grp * 8);
                *reinterpret_cast<uint4*>(g_gtop + (size_t)node * HID + grp * 8) = vt;
            }
        }
        #pragma unroll
        for (int p = 0; p < 8; p++) {
            int cidx = tid + p * 512;
            int r = cidx >> 5, ln = cidx & 31;
            int node = node0 + r;
            if (node < N_ATOMS) {
                uint2 v;
                v.x = *reinterpret_cast<uint32_t*>(sg_gb + r * STG_STRIDE + 2 * ln);
                v.y = *reinterpret_cast<uint32_t*>(sg_ln + r * STG_STRIDE + 2 * ln);
                g_gl[(size_t)node * 32 + ln] = v;
            }
        }

        t = tn;
        buf ^= 1;
    }
}

// ---------------------------------------------------------------------------
// 4. Gather-aggregate + fused node update (r12-proven).
// ---------------------------------------------------------------------------
__global__ void __launch_bounds__(256) gather_kernel() {
    int w = (blockIdx.x * 256 + threadIdx.x) >> 5;
    int l = threadIdx.x & 31;
    if (w >= N_ATOMS) return;

    int beg = __ldg(&g_off[w]);
    int end = __ldg(&g_off[w + 1]);

    __half2 gt = reinterpret_cast<const __half2*>(g_gtop)[(size_t)w * 32 + l];
    uint2 self = __ldg(&g_gl[(size_t)w * 32 + l]);
    float2 acc = __half22float2(*reinterpret_cast<__half2*>(&self.y));

    for (int base = beg; base < end; base += 32) {
        int myc = (base + l < end) ? g_scol[base + l] : 0;
        int m = min(32, end - base);
        #pragma unroll 4
        for (int j = 0; j < m; j++) {
            int cc = __shfl_sync(0xffffffffu, myc, j);
            uint2 v = __ldg(&g_gl[(size_t)cc * 32 + l]);
            __half2 gb = *reinterpret_cast<__half2*>(&v.x);
            __half2 lh = *reinterpret_cast<__half2*>(&v.y);
            __half2 pre = __hadd2(gt, gb);
            uint32_t th_u;
            asm("tanh.approx.f16x2 %0, %1;"
                : "=r"(th_u) : "r"(*reinterpret_cast<uint32_t*>(&pre)));
            __half2 th = *reinterpret_cast<__half2*>(&th_u);
            __half2 msg = __hfma2(th, lh, lh);       // (tanh+1)*linh, fp16
            float2 mf = __half22float2(msg);
            acc.x += 0.5f * mf.x;                    // FFMA-imm
            acc.y += 0.5f * mf.y;
        }
    }

    __half2* xo = reinterpret_cast<__half2*>(g_xh);
    xo[(size_t)w * 32 + l] = __floats2half2_rn(fmaxf(acc.x, 0.0f), fmaxf(acc.y, 0.0f));
}

// ---------------------------------------------------------------------------
// 5. Mean pool (grid=512, half2-vectorized loads)
// ---------------------------------------------------------------------------
__global__ void __launch_bounds__(256) pool_kernel() {
    int t = threadIdx.x;
    int c2 = t & 31;      // half2 column index (covers 64 cols)
    int grp = t >> 5;     // 8 node groups per block
    float2 acc = make_float2(0.0f, 0.0f);
    const __half2* x2 = reinterpret_cast<const __half2*>(g_xh);
    for (int node = blockIdx.x * 8 + grp; node < N_ATOMS; node += gridDim.x * 8) {
        float2 v = __half22float2(x2[(size_t)node * 32 + c2]);
        acc.x += v.x;
        acc.y += v.y;
    }
    __shared__ float2 s[256];
    s[t] = acc;
    __syncthreads();
    if (grp == 0) {
        float2 r = s[c2];
        #pragma unroll
        for (int g = 1; g < 8; g++) {
            r.x += s[g * 32 + c2].x;
            r.y += s[g * 32 + c2].y;
        }
        atomicAdd(&g_pooled[2 * c2], r.x);
        atomicAdd(&g_pooled[2 * c2 + 1], r.y);
    }
}

// ---------------------------------------------------------------------------
// 6. MLP head
// ---------------------------------------------------------------------------
__global__ void head_kernel(const float* __restrict__ W1, const float* __restrict__ b1,
                            const float* __restrict__ W2, const float* __restrict__ b2,
                            float* __restrict__ out) {
    __shared__ float sp[64], sh[64];
    int t = threadIdx.x;
    if (t < 64) sp[t] = g_pooled[t] * (1.0f / (float)N_ATOMS);
    __syncthreads();
    if (t < 64) {
        float a = b1[t];
        #pragma unroll
        for (int k = 0; k < 64; k++) a += sp[k] * W1[k * 64 + t];
        sh[t] = fmaxf(a, 0.0f);
    }
    __syncthreads();
    if (t < 128) {
        float a = b2[t];
        #pragma unroll
        for (int k = 0; k < 64; k++) a += sh[k] * W2[k * 128 + t];
        out[t] = a;
    }
}

// ---------------------------------------------------------------------------
static cudaStream_t g_s1 = nullptr;
static cudaEvent_t  g_evF = nullptr, g_evJ = nullptr;
static int g_init = 0;

extern "C" void kernel_launch(void* const* d_in, const int* in_sizes, int n_in,
                              void* d_out, int out_size) {
    const int*   an  = (const int*)d_in[0];
    const int*   ei  = (const int*)d_in[3];
    const float* emb = (const float*)d_in[4];
    const float* Wl  = (const float*)d_in[5];
    const float* bl  = (const float*)d_in[6];
    const float* Wg  = (const float*)d_in[7];
    const float* bg  = (const float*)d_in[8];
    const float* W1  = (const float*)d_in[9];
    const float* b1  = (const float*)d_in[10];
    const float* W2  = (const float*)d_in[11];
    const float* b2  = (const float*)d_in[12];
    float* out = (float*)d_out;

    if (!g_init) {
        g_init = 1;
        if (cudaStreamCreateWithFlags(&g_s1, cudaStreamNonBlocking) != cudaSuccess) g_s1 = nullptr;
        if (g_s1) {
            cudaEventCreateWithFlags(&g_evF, cudaEventDisableTiming);
            cudaEventCreateWithFlags(&g_evJ, cudaEventDisableTiming);
        }
        cudaFuncSetAttribute(proj_kernel, cudaFuncAttributeMaxDynamicSharedMemorySize, PROJ_SMEM);
    }

    const int embedBlocks = (N_EDGES + 255) / 256;            // 3907 (covers 800k + 1M)
    const int edgeBlocks = (N_EDGES + 255) / 256;             // 3907
    const int gatherBlocks = (N_ATOMS * 32 + 255) / 256;      // 12500
    const bool fork = (g_s1 != nullptr);
    cudaStream_t s1 = fork ? g_s1 : (cudaStream_t)0;

    wconv_kernel<<<400, 256>>>(Wg, Wl);                       // zeros g_cnt/pooled
    embed_kernel<<<embedBlocks, 256>>>(an, emb, ei);          // xh (vectorized) + hist

    if (fork) {
        cudaEventRecord(g_evF, 0);
        cudaStreamWaitEvent(s1, g_evF, 0);
    }
    // sort chain on side stream; overlaps proj0
    scan_a_kernel<<<SCAN_NB, SCAN_T, 0, s1>>>();
    scan_c_kernel<<<SCAN_NB, SCAN_T, 0, s1>>>();
    scatter_kernel<<<edgeBlocks, 256, 0, s1>>>(ei);
    if (fork) cudaEventRecord(g_evJ, s1);

    proj_kernel<<<PROJ_GRID, 512, PROJ_SMEM>>>(0, bg, bl);    // main stream

    if (fork) cudaStreamWaitEvent(0, g_evJ, 0);
    gather_kernel<<<gatherBlocks, 256>>>();

    for (int l = 1; l < 3; l++) {
        proj_kernel<<<PROJ_GRID, 512, PROJ_SMEM>>>(l, bg + l * 64, bl + l * 64);
        gather_kernel<<<gatherBlocks, 256>>>();
    }
    pool_kernel<<<512, 256>>>();
    head_kernel<<<1, 128>>>(W1, b1, W2, b2, out);
}

// round 16
// speedup vs baseline: 1.1182x; 1.0346x over previous
#include <cuda_runtime.h>
#include <cuda_fp16.h>
#include <cstdint>

// Problem constants
#define N_ATOMS 100000
#define N_EDGES 1000000
#define HID 64
#define OUTD 128
#define NTILES 1563          // ceil(N_ATOMS / 64)
#define PROJ_GRID 296        // 2 blocks/SM x 148

#define SCAN_T 512
#define SCAN_ITEMS (N_ATOMS + 1)
#define SCAN_NB ((SCAN_ITEMS + SCAN_T - 1) / SCAN_T)

// Scratch (device globals: allocation-free rule)
__device__ __half g_xh[N_ATOMS * HID];     // node features, fp16 (MMA A operand)
__device__ __half g_gtop[N_ATOMS * HID];   // 0.5*(x @ Wg_top + b_gate)
__device__ uint2  g_gl[N_ATOMS * 32];      // per (node,lane): {0.5*gbot half2, linh half2}
__device__ __half g_wf[3 * 64 * 192];      // fused fp16 weights per layer
__device__ float  g_pooled[HID];

// Edge CSR (built per launch by counting sort)
__device__ int g_cnt[SCAN_ITEMS];
__device__ int g_off[SCAN_ITEMS];
__device__ int g_cur[N_ATOMS];
__device__ int g_part[SCAN_NB];
__device__ int g_scol[N_EDGES];

static __device__ __forceinline__ uint32_t cvta_s(const void* p) {
    uint32_t r;
    asm("{ .reg .u64 t; cvta.to.shared.u64 t, %1; cvt.u32.u64 %0, t; }" : "=r"(r) : "l"(p));
    return r;
}

// ---------------------------------------------------------------------------
// 0. Weight preconvert + zero g_cnt/g_pooled (runs FIRST)
// ---------------------------------------------------------------------------
__global__ void __launch_bounds__(256) wconv_kernel(const float* __restrict__ Wg,
                                                    const float* __restrict__ Wl) {
    int i = blockIdx.x * 256 + threadIdx.x;
    if (i < 3 * 64 * 192) {
        int lay = i / (64 * 192);
        int rem = i - lay * (64 * 192);
        int k = rem / 192, c = rem - k * 192;
        float w;
        if (c < 64)       w = Wg[lay * 128 * 64 + k * 64 + c];
        else if (c < 128) w = Wg[lay * 128 * 64 + (64 + k) * 64 + (c - 64)];
        else              w = Wl[lay * 64 * 64 + k * 64 + (c - 128)];
        g_wf[i] = __float2half(w);
    }
    if (i < SCAN_ITEMS) g_cnt[i] = 0;
    if (i < HID) g_pooled[i] = 0.0f;
}

// ---------------------------------------------------------------------------
// 1. Embedding lookup (vectorized: 8 ch/thread, STG.128) + edge histogram
// ---------------------------------------------------------------------------
__global__ void __launch_bounds__(256) embed_kernel(const int* __restrict__ an,
                                                    const float* __restrict__ emb,
                                                    const int* __restrict__ ei) {
    int i = blockIdx.x * 256 + threadIdx.x;
    if (i < N_ATOMS * 8) {
        int v = i >> 3, ch = i & 7;
        const float4* e4 = reinterpret_cast<const float4*>(
            emb + (size_t)__ldg(&an[v]) * HID + ch * 8);
        float4 f0 = __ldg(&e4[0]), f1 = __ldg(&e4[1]);
        __half2 h[4];
        h[0] = __floats2half2_rn(f0.x, f0.y);
        h[1] = __floats2half2_rn(f0.z, f0.w);
        h[2] = __floats2half2_rn(f1.x, f1.y);
        h[3] = __floats2half2_rn(f1.z, f1.w);
        *reinterpret_cast<uint4*>(g_xh + (size_t)v * HID + ch * 8) =
            *reinterpret_cast<uint4*>(h);
    }
    if (i < N_EDGES) atomicAdd(&g_cnt[ei[i]], 1);
}

// ---------------------------------------------------------------------------
// 2. Scan (a: block sums; c: fused partial-scan + local scan) + scatter
// ---------------------------------------------------------------------------
__global__ void __launch_bounds__(SCAN_T) scan_a_kernel() {
    __shared__ int s[SCAN_T];
    int t = threadIdx.x;
    int i = blockIdx.x * SCAN_T + t;
    s[t] = (i < SCAN_ITEMS) ? g_cnt[i] : 0;
    __syncthreads();
    for (int d = SCAN_T / 2; d > 0; d >>= 1) {
        if (t < d) s[t] += s[t + d];
        __syncthreads();
    }
    if (t == 0) g_part[blockIdx.x] = s[0];
}

__global__ void __launch_bounds__(SCAN_T) scan_c_kernel() {
    __shared__ int s[SCAN_T];
    __shared__ int p[256];
    int t = threadIdx.x;
    int i = blockIdx.x * SCAN_T + t;

    if (t < 256) p[t] = (t < SCAN_NB) ? g_part[t] : 0;
    __syncthreads();
    for (int d = 1; d < 256; d <<= 1) {
        int a = 0;
        if (t < 256 && t >= d) a = p[t - d];
        __syncthreads();
        if (t < 256) p[t] += a;
        __syncthreads();
    }
    int prefix = (blockIdx.x == 0) ? 0 : p[blockIdx.x - 1];

    int v = (i < SCAN_ITEMS) ? g_cnt[i] : 0;
    s[t] = v;
    __syncthreads();
    for (int d = 1; d < SCAN_T; d <<= 1) {
        int a = (t >= d) ? s[t - d] : 0;
        __syncthreads();
        s[t] += a;
        __syncthreads();
    }
    int off = prefix + s[t] - v;  // exclusive
    if (i < SCAN_ITEMS) g_off[i] = off;
    if (i < N_ATOMS)    g_cur[i] = off;
}

__global__ void __launch_bounds__(256) scatter_kernel(const int* __restrict__ ei) {
    int e = blockIdx.x * 256 + threadIdx.x;
    if (e < N_EDGES) {
        int r = ei[e];
        int c = ei[N_EDGES + e];
        int p = atomicAdd(&g_cur[r], 1);
        g_scol[p] = c;
    }
}

// ---------------------------------------------------------------------------
// 3. Persistent tensor-core projection, v3: 64-node tiles, 256 thr,
//    2 blocks/SM (regs capped, smem 72KB). 8 warps = 2(m) x 4(n);
//    warp = 32 rows x 48 cols. cp.async double-buffered A tiles.
// ---------------------------------------------------------------------------
#define WS_STRIDE 200
#define XS_STRIDE 72
#define STG_STRIDE 72
#define WS_BYTES   (64 * WS_STRIDE * 2)          // 25600
#define XS_OFF     WS_BYTES
#define XS_BUF_BYTES (64 * XS_STRIDE * 2)        // 9216
#define STG_OFF    (XS_OFF + 2 * XS_BUF_BYTES)   // 44032
#define SG_GT_OFF  STG_OFF
#define SG_GB_OFF  (STG_OFF + 64 * STG_STRIDE * 2)
#define SG_LN_OFF  (STG_OFF + 2 * 64 * STG_STRIDE * 2)
#define BIAS_OFF   (STG_OFF + 3 * 64 * STG_STRIDE * 2)   // 71680
#define PROJ_SMEM  (BIAS_OFF + 512)                       // 72192

static __device__ __forceinline__ void prefetch_tile(int tile, int buf, int tid,
                                                     uint32_t xs_base_u) {
    int n0 = tile * 64;
    #pragma unroll
    for (int p = 0; p < 2; p++) {
        int idx = tid + p * 256;
        int r = idx >> 3, grp = idx & 7;
        int node = n0 + r;
        int node_c = node < N_ATOMS ? node : N_ATOMS - 1;
        uint32_t dst = xs_base_u + buf * XS_BUF_BYTES + (r * XS_STRIDE + grp * 8) * 2;
        const void* src = g_xh + (size_t)node_c * HID + grp * 8;
        int sz = (node < N_ATOMS) ? 16 : 0;
        asm volatile("cp.async.cg.shared.global [%0], [%1], 16, %2;"
                     :: "r"(dst), "l"(src), "r"(sz));
    }
    asm volatile("cp.async.commit_group;");
}

__global__ void __launch_bounds__(256, 2) proj_kernel(int layer,
                                                      const float* __restrict__ bg,
                                                      const float* __restrict__ bl) {
    extern __shared__ __align__(16) char smraw[];
    __half* ws    = (__half*)smraw;                   // [64][200]
    __half* sg_gt = (__half*)(smraw + SG_GT_OFF);     // [64][72]
    __half* sg_gb = (__half*)(smraw + SG_GB_OFF);     // [64][72]
    __half* sg_ln = (__half*)(smraw + SG_LN_OFF);     // [64][72]
    float*  bgs   = (float*)(smraw + BIAS_OFF);
    float*  bls   = bgs + 64;

    const int tid = threadIdx.x;
    const __half* wf = g_wf + layer * 64 * 192;

    for (int i = tid; i < 1536; i += 256) {
        int k = i / 24, grp = i - k * 24;
        *reinterpret_cast<uint4*>(ws + k * WS_STRIDE + grp * 8) =
            *reinterpret_cast<const uint4*>(wf + k * 192 + grp * 8);
    }
    if (tid < 64) { bgs[tid] = bg[tid]; bls[tid] = bl[tid]; }

    const uint32_t xs_base_u = cvta_s(smraw + XS_OFF);
    const uint32_t ws_u = cvta_s(ws);

    const int wid = tid >> 5, l = tid & 31;
    const int wm = wid & 1;    // rows wm*32 .. +31
    const int wn = wid >> 1;   // cols wn*48 .. +47
    const uint32_t b_base = ws_u + ((l & 15) * WS_STRIDE + wn * 48) * 2;
    const int qid = l >> 2, tig = l & 3;

    int t = blockIdx.x;
    int buf = 0;
    if (t < NTILES) prefetch_tile(t, 0, tid, xs_base_u);

    while (t < NTILES) {
        int tn = t + PROJ_GRID;
        asm volatile("cp.async.wait_group 0;");
        __syncthreads();

        float acc[2][6][4];
        #pragma unroll
        for (int mi = 0; mi < 2; mi++)
            #pragma unroll
            for (int ni = 0; ni < 6; ni++)
                #pragma unroll
                for (int q = 0; q < 4; q++) acc[mi][ni][q] = 0.0f;

        const uint32_t a_base = xs_base_u + buf * XS_BUF_BYTES +
                                ((wm * 32 + (l & 15)) * XS_STRIDE + (l >> 4) * 8) * 2;
        #pragma unroll
        for (int kk = 0; kk < 4; kk++) {
            uint32_t b[6][2];
            uint32_t bstep = b_base + kk * 16 * WS_STRIDE * 2;
            #pragma unroll
            for (int ni = 0; ni < 6; ni++) {
                asm volatile("ldmatrix.sync.aligned.m8n8.x2.trans.shared.b16 {%0,%1}, [%2];"
                             : "=r"(b[ni][0]), "=r"(b[ni][1]) : "r"(bstep + ni * 8 * 2));
            }
            uint32_t astep = a_base + kk * 16 * 2;
            #pragma unroll
            for (int mi = 0; mi < 2; mi++) {
                uint32_t a0, a1, a2, a3;
                asm volatile("ldmatrix.sync.aligned.m8n8.x4.shared.b16 {%0,%1,%2,%3}, [%4];"
                             : "=r"(a0), "=r"(a1), "=r"(a2), "=r"(a3)
                             : "r"(astep + mi * 16 * XS_STRIDE * 2));
                #pragma unroll
                for (int ni = 0; ni < 6; ni++) {
                    asm volatile(
                        "mma.sync.aligned.m16n8k16.row.col.f32.f16.f16.f32 "
                        "{%0,%1,%2,%3},{%4,%5,%6,%7},{%8,%9},{%0,%1,%2,%3};"
                        : "+f"(acc[mi][ni][0]), "+f"(acc[mi][ni][1]),
                          "+f"(acc[mi][ni][2]), "+f"(acc[mi][ni][3])
                        : "r"(a0), "r"(a1), "r"(a2), "r"(a3), "r"(b[ni][0]), "r"(b[ni][1]));
                }
            }
        }

        if (tn < NTILES) prefetch_tile(tn, buf ^ 1, tid, xs_base_u);

        // Stage fragments (fp16; gtop/gbot pre-scaled by 0.5 for f16x2 tanh)
        #pragma unroll
        for (int mi = 0; mi < 2; mi++) {
            int r0 = wm * 32 + mi * 16 + qid;
            int r1 = r0 + 8;
            #pragma unroll
            for (int ni = 0; ni < 6; ni++) {
                int c = wn * 48 + ni * 8 + tig * 2;
                float d0 = acc[mi][ni][0], d1 = acc[mi][ni][1];
                float d2 = acc[mi][ni][2], d3 = acc[mi][ni][3];
                if (c < 64) {
                    float b0v = bgs[c], b1v = bgs[c + 1];
                    *reinterpret_cast<__half2*>(sg_gt + r0 * STG_STRIDE + c) =
                        __floats2half2_rn(0.5f * (d0 + b0v), 0.5f * (d1 + b1v));
                    *reinterpret_cast<__half2*>(sg_gt + r1 * STG_STRIDE + c) =
                        __floats2half2_rn(0.5f * (d2 + b0v), 0.5f * (d3 + b1v));
                } else if (c < 128) {
                    int cc = c - 64;
                    *reinterpret_cast<__half2*>(sg_gb + r0 * STG_STRIDE + cc) =
                        __floats2half2_rn(0.5f * d0, 0.5f * d1);
                    *reinterpret_cast<__half2*>(sg_gb + r1 * STG_STRIDE + cc) =
                        __floats2half2_rn(0.5f * d2, 0.5f * d3);
                } else {
                    int cc = c - 128;
                    float b0v = bls[cc], b1v = bls[cc + 1];
                    *reinterpret_cast<__half2*>(sg_ln + r0 * STG_STRIDE + cc) =
                        __floats2half2_rn(d0 + b0v, d1 + b1v);
                    *reinterpret_cast<__half2*>(sg_ln + r1 * STG_STRIDE + cc) =
                        __floats2half2_rn(d2 + b0v, d3 + b1v);
                }
            }
        }
        __syncthreads();

        const int node0 = t * 64;
        // gtop write-out: 512 uint4 chunks
        #pragma unroll
        for (int p = 0; p < 2; p++) {
            int cidx = tid + p * 256;
            int r = cidx >> 3, grp = cidx & 7;
            int node = node0 + r;
            if (node < N_ATOMS) {
                uint4 vt = *reinterpret_cast<uint4*>(sg_gt + r * STG_STRIDE + grp * 8);
                *reinterpret_cast<uint4*>(g_gtop + (size_t)node * HID + grp * 8) = vt;
            }
        }
        // interleaved {gbot, linh} write-out: 2048 uint2
        #pragma unroll
        for (int p = 0; p < 8; p++) {
            int cidx = tid + p * 256;
            int r = cidx >> 5, ln = cidx & 31;
            int node = node0 + r;
            if (node < N_ATOMS) {
                uint2 v;
                v.x = *reinterpret_cast<uint32_t*>(sg_gb + r * STG_STRIDE + 2 * ln);
                v.y = *reinterpret_cast<uint32_t*>(sg_ln + r * STG_STRIDE + 2 * ln);
                g_gl[(size_t)node * 32 + ln] = v;
            }
        }

        t = tn;
        buf ^= 1;
    }
}

// ---------------------------------------------------------------------------
// 4. Gather-aggregate + fused node update (r12-proven).
// ---------------------------------------------------------------------------
__global__ void __launch_bounds__(256) gather_kernel() {
    int w = (blockIdx.x * 256 + threadIdx.x) >> 5;
    int l = threadIdx.x & 31;
    if (w >= N_ATOMS) return;

    int beg = __ldg(&g_off[w]);
    int end = __ldg(&g_off[w + 1]);

    __half2 gt = reinterpret_cast<const __half2*>(g_gtop)[(size_t)w * 32 + l];
    uint2 self = __ldg(&g_gl[(size_t)w * 32 + l]);
    float2 acc = __half22float2(*reinterpret_cast<__half2*>(&self.y));

    for (int base = beg; base < end; base += 32) {
        int myc = (base + l < end) ? g_scol[base + l] : 0;
        int m = min(32, end - base);
        #pragma unroll 4
        for (int j = 0; j < m; j++) {
            int cc = __shfl_sync(0xffffffffu, myc, j);
            uint2 v = __ldg(&g_gl[(size_t)cc * 32 + l]);
            __half2 gb = *reinterpret_cast<__half2*>(&v.x);
            __half2 lh = *reinterpret_cast<__half2*>(&v.y);
            __half2 pre = __hadd2(gt, gb);
            uint32_t th_u;
            asm("tanh.approx.f16x2 %0, %1;"
                : "=r"(th_u) : "r"(*reinterpret_cast<uint32_t*>(&pre)));
            __half2 th = *reinterpret_cast<__half2*>(&th_u);
            __half2 msg = __hfma2(th, lh, lh);       // (tanh+1)*linh, fp16
            float2 mf = __half22float2(msg);
            acc.x += 0.5f * mf.x;                    // FFMA-imm
            acc.y += 0.5f * mf.y;
        }
    }

    __half2* xo = reinterpret_cast<__half2*>(g_xh);
    xo[(size_t)w * 32 + l] = __floats2half2_rn(fmaxf(acc.x, 0.0f), fmaxf(acc.y, 0.0f));
}

// ---------------------------------------------------------------------------
// 5. Mean pool (grid=512, half2-vectorized loads)
// ---------------------------------------------------------------------------
__global__ void __launch_bounds__(256) pool_kernel() {
    int t = threadIdx.x;
    int c2 = t & 31;
    int grp = t >> 5;
    float2 acc = make_float2(0.0f, 0.0f);
    const __half2* x2 = reinterpret_cast<const __half2*>(g_xh);
    for (int node = blockIdx.x * 8 + grp; node < N_ATOMS; node += gridDim.x * 8) {
        float2 v = __half22float2(x2[(size_t)node * 32 + c2]);
        acc.x += v.x;
        acc.y += v.y;
    }
    __shared__ float2 s[256];
    s[t] = acc;
    __syncthreads();
    if (grp == 0) {
        float2 r = s[c2];
        #pragma unroll
        for (int g = 1; g < 8; g++) {
            r.x += s[g * 32 + c2].x;
            r.y += s[g * 32 + c2].y;
        }
        atomicAdd(&g_pooled[2 * c2], r.x);
        atomicAdd(&g_pooled[2 * c2 + 1], r.y);
    }
}

// ---------------------------------------------------------------------------
// 6. MLP head
// ---------------------------------------------------------------------------
__global__ void head_kernel(const float* __restrict__ W1, const float* __restrict__ b1,
                            const float* __restrict__ W2, const float* __restrict__ b2,
                            float* __restrict__ out) {
    __shared__ float sp[64], sh[64];
    int t = threadIdx.x;
    if (t < 64) sp[t] = g_pooled[t] * (1.0f / (float)N_ATOMS);
    __syncthreads();
    if (t < 64) {
        float a = b1[t];
        #pragma unroll
        for (int k = 0; k < 64; k++) a += sp[k] * W1[k * 64 + t];
        sh[t] = fmaxf(a, 0.0f);
    }
    __syncthreads();
    if (t < 128) {
        float a = b2[t];
        #pragma unroll
        for (int k = 0; k < 64; k++) a += sh[k] * W2[k * 128 + t];
        out[t] = a;
    }
}

// ---------------------------------------------------------------------------
static cudaStream_t g_s1 = nullptr;
static cudaEvent_t  g_evF = nullptr, g_evJ = nullptr;
static int g_init = 0;

extern "C" void kernel_launch(void* const* d_in, const int* in_sizes, int n_in,
                              void* d_out, int out_size) {
    const int*   an  = (const int*)d_in[0];
    const int*   ei  = (const int*)d_in[3];
    const float* emb = (const float*)d_in[4];
    const float* Wl  = (const float*)d_in[5];
    const float* bl  = (const float*)d_in[6];
    const float* Wg  = (const float*)d_in[7];
    const float* bg  = (const float*)d_in[8];
    const float* W1  = (const float*)d_in[9];
    const float* b1  = (const float*)d_in[10];
    const float* W2  = (const float*)d_in[11];
    const float* b2  = (const float*)d_in[12];
    float* out = (float*)d_out;

    if (!g_init) {
        g_init = 1;
        if (cudaStreamCreateWithFlags(&g_s1, cudaStreamNonBlocking) != cudaSuccess) g_s1 = nullptr;
        if (g_s1) {
            cudaEventCreateWithFlags(&g_evF, cudaEventDisableTiming);
            cudaEventCreateWithFlags(&g_evJ, cudaEventDisableTiming);
        }
        cudaFuncSetAttribute(proj_kernel, cudaFuncAttributeMaxDynamicSharedMemorySize, PROJ_SMEM);
    }

    const int embedBlocks = (N_EDGES + 255) / 256;            // 3907 (covers 800k + 1M)
    const int edgeBlocks = (N_EDGES + 255) / 256;             // 3907
    const int gatherBlocks = (N_ATOMS * 32 + 255) / 256;      // 12500
    const bool fork = (g_s1 != nullptr);
    cudaStream_t s1 = fork ? g_s1 : (cudaStream_t)0;

    wconv_kernel<<<400, 256>>>(Wg, Wl);                       // zeros g_cnt/pooled
    embed_kernel<<<embedBlocks, 256>>>(an, emb, ei);          // xh (vectorized) + hist

    if (fork) {
        cudaEventRecord(g_evF, 0);
        cudaStreamWaitEvent(s1, g_evF, 0);
    }
    // sort chain on side stream; overlaps proj0
    scan_a_kernel<<<SCAN_NB, SCAN_T, 0, s1>>>();
    scan_c_kernel<<<SCAN_NB, SCAN_T, 0, s1>>>();
    scatter_kernel<<<edgeBlocks, 256, 0, s1>>>(ei);
    if (fork) cudaEventRecord(g_evJ, s1);

    proj_kernel<<<PROJ_GRID, 256, PROJ_SMEM>>>(0, bg, bl);    // main stream

    if (fork) cudaStreamWaitEvent(0, g_evJ, 0);
    gather_kernel<<<gatherBlocks, 256>>>();

    for (int l = 1; l < 3; l++) {
        proj_kernel<<<PROJ_GRID, 256, PROJ_SMEM>>>(l, bg + l * 64, bl + l * 64);
        gather_kernel<<<gatherBlocks, 256>>>();
    }
    pool_kernel<<<512, 256>>>();
    head_kernel<<<1, 128>>>(W1, b1, W2, b2, out);
}